// round 2
// baseline (speedup 1.0000x reference)
#include <cuda_runtime.h>
#include <cstdint>

#define DEV __device__ __forceinline__

// ---------------- problem dims ----------------
#define BB    64
#define SEQ   2048
#define EE    512      // ENC_H == DEC_H
#define AA    512      // ATTN
#define RTOT  (BB*SEQ) // 131072 rows
#define MT    128      // CTA rows
#define NCH   256      // CTA cols per n-chunk (2 chunks cover AA)
#define KS    64       // k-slice per pipeline stage
#define NSTG  (EE/KS)  // 8 stages
#define APAD  (KS+4)   // padded row stride in floats (bank-conflict-free)
#define ABYTES (MT*APAD*4)    // 34816
#define WBYTES (NCH*APAD*4)   // 69632
#define BUFB   (ABYTES+WBYTES)
#define OFF_TILE 4096         // bias(256f)+v(256f)+partials(512f)+pad
#define SMEMTOT (OFF_TILE + 2*BUFB)  // 212992 bytes
#define NCHUNK 16      // context partial chunks per batch

// ---------------- scratch ----------------
__device__ float g_dec_proj[BB*AA];
__device__ float g_scores2[2*RTOT];          // partial scores per n-chunk
__device__ float g_partial[BB*NCHUNK*EE];

// ---------------- helpers ----------------
DEV uint32_t smem_u32(const void* p) {
    uint32_t a;
    asm("{ .reg .u64 t; cvta.to.shared.u64 t, %1; cvt.u32.u64 %0, t; }" : "=r"(a) : "l"(p));
    return a;
}
DEV void cp16(uint32_t dst, const void* src) {
    asm volatile("cp.async.cg.shared.global [%0], [%1], 16;\n" :: "r"(dst), "l"(src));
}
DEV void cp_commit() { asm volatile("cp.async.commit_group;\n" ::); }
template<int N> DEV void cp_wait() { asm volatile("cp.async.wait_group %0;\n" :: "n"(N)); }

DEV uint32_t to_tf32(float x) {
    uint32_t r;
    asm("cvt.rna.tf32.f32 %0, %1;" : "=r"(r) : "f"(x));
    return r;
}
DEV void mma_tf32(float* d, const uint32_t* a, const uint32_t* b) {
    asm volatile(
        "mma.sync.aligned.m16n8k8.row.col.f32.tf32.tf32.f32 "
        "{%0,%1,%2,%3}, {%4,%5,%6,%7}, {%8,%9}, {%0,%1,%2,%3};"
        : "+f"(d[0]), "+f"(d[1]), "+f"(d[2]), "+f"(d[3])
        : "r"(a[0]), "r"(a[1]), "r"(a[2]), "r"(a[3]), "r"(b[0]), "r"(b[1]));
}
DEV float fast_tanh(float x) {
    // tanh(x) = 1 - 2/(exp(2x)+1); __expf handles saturation to +-1
    float e = __expf(2.f * x);
    return 1.f - __fdividef(2.f, e + 1.f);
}

// ================= kernel A: dec_proj[b,a] = dec[b,:] . W_dec[a,:] =================
__global__ __launch_bounds__(256) void decproj_kernel(
    const float* __restrict__ dec, const float* __restrict__ Wdec)
{
    __shared__ float sd[EE];
    int b = blockIdx.x, tid = threadIdx.x;
    sd[tid]       = dec[b*EE + tid];
    sd[tid + 256] = dec[b*EE + tid + 256];
    __syncthreads();
    int w = tid >> 5, lane = tid & 31;
    for (int a = w; a < AA; a += 8) {
        const float* wr = Wdec + a*EE;
        float acc = 0.f;
        #pragma unroll 8
        for (int k = lane; k < EE; k += 32) acc = fmaf(sd[k], wr[k], acc);
        #pragma unroll
        for (int o = 16; o; o >>= 1) acc += __shfl_xor_sync(~0u, acc, o);
        if (lane == 0) g_dec_proj[b*AA + a] = acc;
    }
}

// ================= kernel B: partial scores via tf32 mma.sync ======================
// CTA tile: M=128 rows x N=256 attn dims (n-chunk), K=512 streamed.
// 8 warps as 2(M) x 4(N); warp tile m64 x n64; acc 128 regs/thread.
__global__ __launch_bounds__(256, 1) void score_kernel(
    const float* __restrict__ enc, const float* __restrict__ Wenc,
    const float* __restrict__ vvec)
{
    extern __shared__ float sm[];
    float* smb = sm;           // 256: bias chunk
    float* smv = sm + 256;     // 256: v chunk
    float* smp = sm + 512;     // 512: per-warp-col row partials
    const uint32_t sbase = smem_u32(sm);

    const int tid  = threadIdx.x;
    const int bx   = blockIdx.x;
    const int tile = bx >> 1;
    const int nch  = bx & 1;
    const int row_base = tile * MT;
    const int b_idx = row_base / SEQ;

    const int lane = tid & 31;
    const int wid  = tid >> 5;
    const int wm   = wid >> 2;       // 0..1  (M warp row)
    const int wn   = wid & 3;        // 0..3  (N warp col)
    const int g    = lane >> 2;      // 0..7
    const int tg   = lane & 3;       // 0..3

    // stage bias + v for this n-chunk
    if (tid < 256) {
        smb[tid] = g_dec_proj[b_idx*AA + nch*NCH + tid];
        smv[tid] = vvec[nch*NCH + tid];
    }

    // ---- async stage loader ----
    const float* wbase = Wenc + (size_t)(nch*NCH) * EE;
    auto load_stage = [&](int s, int b) {
        const uint32_t abuf = sbase + OFF_TILE + b*BUFB;
        const uint32_t wbuf = abuf + ABYTES;
        const float* asrc = enc + (size_t)row_base*EE + s*KS;
        const float* wsrc = wbase + s*KS;
        #pragma unroll
        for (int i = 0; i < 8; i++) {            // 128 rows x 16 float4
            int id = tid + i*256; int r = id >> 4, c = id & 15;
            cp16(abuf + (uint32_t)(r*APAD + c*4)*4, asrc + (size_t)r*EE + c*4);
        }
        #pragma unroll
        for (int i = 0; i < 16; i++) {           // 256 rows x 16 float4
            int id = tid + i*256; int n = id >> 4, c = id & 15;
            cp16(wbuf + (uint32_t)(n*APAD + c*4)*4, wsrc + (size_t)n*EE + c*4);
        }
        cp_commit();
    };

    float acc[4][8][4];
    #pragma unroll
    for (int i = 0; i < 4; i++)
        #pragma unroll
        for (int j = 0; j < 8; j++)
            #pragma unroll
            for (int c = 0; c < 4; c++) acc[i][j][c] = 0.f;

    load_stage(0, 0);

    #pragma unroll 1
    for (int s = 0; s < NSTG; s++) {
        const int b = s & 1;
        if (s + 1 < NSTG) { load_stage(s + 1, b ^ 1); cp_wait<1>(); }
        else              { cp_wait<0>(); }
        __syncthreads();

        const float* Ab = (const float*)(sm) + (OFF_TILE/4) + b*(BUFB/4);
        const float* Wb = Ab + (ABYTES/4);

        #pragma unroll
        for (int ks = 0; ks < KS/8; ks++) {
            const int k0 = ks * 8;
            uint32_t af[4][4];
            #pragma unroll
            for (int mt = 0; mt < 4; mt++) {
                const int rb = wm*64 + mt*16;
                af[mt][0] = to_tf32(Ab[(rb+g  )*APAD + k0+tg  ]);
                af[mt][1] = to_tf32(Ab[(rb+g+8)*APAD + k0+tg  ]);
                af[mt][2] = to_tf32(Ab[(rb+g  )*APAD + k0+tg+4]);
                af[mt][3] = to_tf32(Ab[(rb+g+8)*APAD + k0+tg+4]);
            }
            uint32_t bf[8][2];
            #pragma unroll
            for (int nt = 0; nt < 8; nt++) {
                const int n = wn*64 + nt*8 + g;
                bf[nt][0] = to_tf32(Wb[n*APAD + k0+tg  ]);
                bf[nt][1] = to_tf32(Wb[n*APAD + k0+tg+4]);
            }
            #pragma unroll
            for (int mt = 0; mt < 4; mt++)
                #pragma unroll
                for (int nt = 0; nt < 8; nt++)
                    mma_tf32(acc[mt][nt], af[mt], bf[nt]);
        }
        __syncthreads();
    }

    // ---- epilogue: tanh(proj + bias) . v  -> per-row partial over this n-chunk ----
    float rp[4][2];
    #pragma unroll
    for (int mt = 0; mt < 4; mt++) { rp[mt][0] = 0.f; rp[mt][1] = 0.f; }

    #pragma unroll
    for (int mt = 0; mt < 4; mt++)
        #pragma unroll
        for (int nt = 0; nt < 8; nt++)
            #pragma unroll
            for (int h = 0; h < 2; h++)
                #pragma unroll
                for (int cc = 0; cc < 2; cc++) {
                    const int col = wn*64 + nt*8 + tg*2 + cc;
                    float x = acc[mt][nt][h*2+cc] + smb[col];
                    rp[mt][h] = fmaf(fast_tanh(x), smv[col], rp[mt][h]);
                }

    // reduce over tg lanes (same row)
    #pragma unroll
    for (int mt = 0; mt < 4; mt++)
        #pragma unroll
        for (int h = 0; h < 2; h++) {
            rp[mt][h] += __shfl_xor_sync(~0u, rp[mt][h], 1);
            rp[mt][h] += __shfl_xor_sync(~0u, rp[mt][h], 2);
        }
    if (tg == 0) {
        #pragma unroll
        for (int mt = 0; mt < 4; mt++)
            #pragma unroll
            for (int h = 0; h < 2; h++)
                smp[wn*128 + wm*64 + mt*16 + h*8 + g] = rp[mt][h];
    }
    __syncthreads();
    if (tid < 128) {
        float sc = smp[tid] + smp[128+tid] + smp[256+tid] + smp[384+tid];
        g_scores2[(size_t)nch*RTOT + row_base + tid] = sc;
    }
}

// ================= kernel C: softmax over S per batch (adds the 2 partials) =======
__global__ __launch_bounds__(256) void softmax_kernel(float* __restrict__ out)
{
    __shared__ float red[256];
    const int b = blockIdx.x, tid = threadIdx.x;
    const float* s0 = g_scores2 + (size_t)b * SEQ;
    const float* s1 = g_scores2 + RTOT + (size_t)b * SEQ;
    float vals[8];
    float m = -1e30f;
    #pragma unroll
    for (int j = 0; j < 8; j++) {
        vals[j] = s0[tid + j*256] + s1[tid + j*256];
        m = fmaxf(m, vals[j]);
    }
    red[tid] = m; __syncthreads();
    for (int st = 128; st; st >>= 1) { if (tid < st) red[tid] = fmaxf(red[tid], red[tid+st]); __syncthreads(); }
    m = red[0]; __syncthreads();
    float sum = 0.f;
    #pragma unroll
    for (int j = 0; j < 8; j++) { vals[j] = __expf(vals[j] - m); sum += vals[j]; }
    red[tid] = sum; __syncthreads();
    for (int st = 128; st; st >>= 1) { if (tid < st) red[tid] += red[tid+st]; __syncthreads(); }
    const float inv = 1.f / red[0];
    float* w = out + BB*EE + (size_t)b*SEQ;
    #pragma unroll
    for (int j = 0; j < 8; j++) w[tid + j*256] = vals[j] * inv;
}

// ================= kernel D: context partials (weights . enc) =================
__global__ __launch_bounds__(128) void context_partial_kernel(
    const float* __restrict__ enc, const float* __restrict__ outw)
{
    __shared__ float ws[128];
    const int b = blockIdx.x >> 4, ch = blockIdx.x & 15, tid = threadIdx.x;
    ws[tid] = outw[(size_t)b*SEQ + ch*128 + tid];
    __syncthreads();
    const float4* ep = (const float4*)enc + (size_t)(b*SEQ + ch*128) * (EE/4) + tid;
    float4 acc = {0.f, 0.f, 0.f, 0.f};
    #pragma unroll 4
    for (int s = 0; s < 128; s++) {
        const float w = ws[s];
        const float4 e = ep[(size_t)s * (EE/4)];
        acc.x = fmaf(w, e.x, acc.x); acc.y = fmaf(w, e.y, acc.y);
        acc.z = fmaf(w, e.z, acc.z); acc.w = fmaf(w, e.w, acc.w);
    }
    ((float4*)g_partial)[(size_t)blockIdx.x * 128 + tid] = acc;
}

// ================= kernel E: reduce partials -> context =================
__global__ __launch_bounds__(128) void context_reduce_kernel(float* __restrict__ out)
{
    const int b = blockIdx.x, tid = threadIdx.x;
    const float4* p = (const float4*)g_partial + (size_t)b * NCHUNK * 128 + tid;
    float4 acc = {0.f, 0.f, 0.f, 0.f};
    #pragma unroll
    for (int c = 0; c < NCHUNK; c++) {
        const float4 t = p[(size_t)c * 128];
        acc.x += t.x; acc.y += t.y; acc.z += t.z; acc.w += t.w;
    }
    ((float4*)out)[b*128 + tid] = acc;
}

// ================= launch =================
extern "C" void kernel_launch(void* const* d_in, const int* in_sizes, int n_in,
                              void* d_out, int out_size)
{
    const float* enc  = (const float*)d_in[0];  // [B,S,E]
    const float* dec  = (const float*)d_in[1];  // [B,D]
    const float* Wenc = (const float*)d_in[2];  // [A,E]
    const float* Wdec = (const float*)d_in[3];  // [A,D]
    const float* v    = (const float*)d_in[4];  // [1,A]
    float* out = (float*)d_out;                 // context [B,E] then weights [B,S]

    static bool attr_set = false;
    if (!attr_set) {
        cudaFuncSetAttribute(score_kernel, cudaFuncAttributeMaxDynamicSharedMemorySize, SMEMTOT);
        attr_set = true;
    }

    decproj_kernel<<<BB, 256>>>(dec, Wdec);
    score_kernel<<<2 * (RTOT/MT), 256, SMEMTOT>>>(enc, Wenc, v);
    softmax_kernel<<<BB, 256>>>(out);
    context_partial_kernel<<<BB * NCHUNK, 128>>>(enc, out + BB*EE);
    context_reduce_kernel<<<BB, 128>>>(out);
}